// round 8
// baseline (speedup 1.0000x reference)
#include <cuda_runtime.h>

// LIF membrane update, single-wave persistent grid-stride:
//   mem_t = (mem_{t-1} - spike_{t-1} * 0.5) * 0.25 + x_t
//   spike_t = rint(clamp(mem_t, 0, 1))   (round-half-to-even, matches jnp.round)
// x: [T=4, N] fp32, out: [T=4, N] fp32, per-element recurrence over t.
//
// R8: exactly one wave (148 SMs x 8 blocks x 256 thr), grid-stride over the
// 2,097,152 float4 positions (~7 iters/thread). Eliminates 6 wave transitions
// + per-wave ramp/drain of the 8192-block launch. Stride is grid-wide so
// every LDG.128/STG.128 stays perfectly lane-contiguous (512B/warp-instr),
// unlike the failed per-thread-ILP variants.

#define DECAY 0.25f
#define T_STEPS 4
#define NUM_SMS 148
#define BLOCKS_PER_SM 8
#define THREADS 256

__global__ __launch_bounds__(THREADS) void lif_kernel(const float4* __restrict__ x,
                                                      float4* __restrict__ out,
                                                      int n4) {
    int stride = gridDim.x * blockDim.x;
    for (int i = blockIdx.x * blockDim.x + threadIdx.x; i < n4; i += stride) {
        float4 mem = make_float4(0.f, 0.f, 0.f, 0.f);
        float4 spk = make_float4(0.f, 0.f, 0.f, 0.f);

#pragma unroll
        for (int t = 0; t < T_STEPS; t++) {
            float4 xi = x[(size_t)t * n4 + i];

            mem.x = fmaf(mem.x - spk.x * 0.5f, DECAY, xi.x);
            mem.y = fmaf(mem.y - spk.y * 0.5f, DECAY, xi.y);
            mem.z = fmaf(mem.z - spk.z * 0.5f, DECAY, xi.z);
            mem.w = fmaf(mem.w - spk.w * 0.5f, DECAY, xi.w);

            spk.x = rintf(fminf(fmaxf(mem.x, 0.f), 1.f));
            spk.y = rintf(fminf(fmaxf(mem.y, 0.f), 1.f));
            spk.z = rintf(fminf(fmaxf(mem.z, 0.f), 1.f));
            spk.w = rintf(fminf(fmaxf(mem.w, 0.f), 1.f));

            out[(size_t)t * n4 + i] = spk;
        }
    }
}

extern "C" void kernel_launch(void* const* d_in, const int* in_sizes, int n_in,
                              void* d_out, int out_size) {
    const float4* x = (const float4*)d_in[0];
    float4* out = (float4*)d_out;

    int n_total = in_sizes[0];        // T * N
    int n4 = (n_total / T_STEPS) / 4; // float4 elements per timestep

    int blocks = NUM_SMS * BLOCKS_PER_SM;  // exactly one wave
    lif_kernel<<<blocks, THREADS>>>(x, out, n4);
}

// round 9
// speedup vs baseline: 1.0842x; 1.0842x over previous
#include <cuda_runtime.h>

// LIF membrane update (FINAL — measured chip roofline):
//   mem_t = (mem_{t-1} - spike_{t-1} * 0.5) * 0.25 + x_t
//   spike_t = rint(clamp(mem_t, 0, 1))   (round-half-to-even, matches jnp.round)
// x: [T=4, N] fp32, out: [T=4, N] fp32, per-element recurrence over t,
// fully fused into a single pass (traffic floor: 268.4 MB, zero reuse).
//
// Roofline evidence (R1-R8, 7 structural variants): ILP=2 strided (64.8%),
// ILP=2 coalesced (72.7%), phase-split+ldcs/stcs (73.9%), block=512 (75.6%),
// persistent single-wave (71.3%) — ALL lose to or tie this naive layout
// (76.2%, 6.03 TB/s, reproduced 4x within 0.13us). Bandwidth is
// pattern-invariant across coalesced variants = path-independent LTS chip
// cap (B300_MICROARCH). No byte removable, no pattern lever remaining.

#define DECAY 0.25f
#define T_STEPS 4

__global__ __launch_bounds__(256) void lif_kernel(const float4* __restrict__ x,
                                                  float4* __restrict__ out,
                                                  int n4) {
    int i = blockIdx.x * blockDim.x + threadIdx.x;
    if (i >= n4) return;

    float4 mem = make_float4(0.f, 0.f, 0.f, 0.f);
    float4 spk = make_float4(0.f, 0.f, 0.f, 0.f);

#pragma unroll
    for (int t = 0; t < T_STEPS; t++) {
        float4 xi = x[(size_t)t * n4 + i];

        mem.x = fmaf(mem.x - spk.x * 0.5f, DECAY, xi.x);
        mem.y = fmaf(mem.y - spk.y * 0.5f, DECAY, xi.y);
        mem.z = fmaf(mem.z - spk.z * 0.5f, DECAY, xi.z);
        mem.w = fmaf(mem.w - spk.w * 0.5f, DECAY, xi.w);

        spk.x = rintf(fminf(fmaxf(mem.x, 0.f), 1.f));
        spk.y = rintf(fminf(fmaxf(mem.y, 0.f), 1.f));
        spk.z = rintf(fminf(fmaxf(mem.z, 0.f), 1.f));
        spk.w = rintf(fminf(fmaxf(mem.w, 0.f), 1.f));

        out[(size_t)t * n4 + i] = spk;
    }
}

extern "C" void kernel_launch(void* const* d_in, const int* in_sizes, int n_in,
                              void* d_out, int out_size) {
    const float4* x = (const float4*)d_in[0];
    float4* out = (float4*)d_out;

    int n_total = in_sizes[0];        // T * N
    int n4 = (n_total / T_STEPS) / 4; // float4 elements per timestep

    int threads = 256;
    int blocks = (n4 + threads - 1) / threads;
    lif_kernel<<<blocks, threads>>>(x, out, n4);
}